// round 2
// baseline (speedup 1.0000x reference)
#include <cuda_runtime.h>
#include <cuda_bf16.h>
#include <mma.h>
#include <math.h>

using namespace nvcuda;

// Problem sizes (fixed by setup_inputs)
#define C        512
#define T        16
#define HW       1024          // 32*32 tokens per frame
#define S_TOT    (T * HW)      // 16384 spatial positions
#define NGROUPS  32
#define CPG      (C / NGROUPS) // 16 channels per group
#define GELEMS   (CPG * S_TOT) // 262144 elements per group
#define EPS      1e-6f

// ---------------- scratch (device globals; allocation-free) ----------------
__device__ float g_H[(size_t)C * S_TOT];   // groupnorm output   [c][s]
__device__ float g_Q[(size_t)C * S_TOT];   // q                  [c][s]
__device__ float g_K[(size_t)C * S_TOT];   // k                  [c][s]
__device__ float g_V[(size_t)C * S_TOT];   // v                  [c][s]
__device__ float g_O[(size_t)C * S_TOT];   // attn output        [c][s]
__device__ float g_P[(size_t)T * HW * HW]; // attn probs         [f][i][j]

// ============================ GroupNorm ============================
__global__ void gn_kernel(const float* __restrict__ x,
                          const float* __restrict__ gamma,
                          const float* __restrict__ beta,
                          float* __restrict__ H) {
    const int g = blockIdx.x;                   // one block per group
    const int tid = threadIdx.x;                // 1024 threads
    const int lane = tid & 31;
    const int wid = tid >> 5;

    const float4* xp = (const float4*)(x + (size_t)g * GELEMS);
    float s = 0.f, ss = 0.f;
    #pragma unroll 4
    for (int i = tid; i < GELEMS / 4; i += blockDim.x) {
        float4 v = xp[i];
        s  += v.x + v.y + v.z + v.w;
        ss += v.x * v.x + v.y * v.y + v.z * v.z + v.w * v.w;
    }
    // block reduce (sum, sumsq)
    __shared__ float sh1[32], sh2[32];
    #pragma unroll
    for (int o = 16; o > 0; o >>= 1) {
        s  += __shfl_xor_sync(0xffffffffu, s, o);
        ss += __shfl_xor_sync(0xffffffffu, ss, o);
    }
    if (lane == 0) { sh1[wid] = s; sh2[wid] = ss; }
    __syncthreads();
    if (wid == 0) {
        s  = sh1[lane];
        ss = sh2[lane];
        #pragma unroll
        for (int o = 16; o > 0; o >>= 1) {
            s  += __shfl_xor_sync(0xffffffffu, s, o);
            ss += __shfl_xor_sync(0xffffffffu, ss, o);
        }
        if (lane == 0) { sh1[0] = s; sh2[0] = ss; }
    }
    __syncthreads();
    const float mean = sh1[0] * (1.0f / GELEMS);
    const float var  = sh2[0] * (1.0f / GELEMS) - mean * mean;
    const float rstd = rsqrtf(var + EPS);

    float4* Hp = (float4*)(H + (size_t)g * GELEMS);
    for (int i = tid; i < GELEMS / 4; i += blockDim.x) {
        float4 v = xp[i];
        const int c = g * CPG + ((i * 4) >> 14);   // 16384 elems per channel
        const float ga = gamma[c] * rstd;
        const float be = beta[c] - mean * ga;
        v.x = v.x * ga + be; v.y = v.y * ga + be;
        v.z = v.z * ga + be; v.w = v.w * ga + be;
        Hp[i] = v;
    }
}

// ============================ tf32 WMMA GEMM ============================
// C[m][n] (+batch) = alpha * sum_k A(m,k) B(k,n) [+ bias[m]] [+ res[m][n]]
// ACOL: A element (m,k) at A + k*lda + m   else A + m*lda + k
// BCOL: B element (k,n) at B + n*ldb + k   else B + k*ldb + n
#define BM 128
#define BN 128
#define BK 32
#define LDA_S 40
#define LDB_S 136
#define LDC_S 136

template <bool ACOL, bool BCOL>
__global__ void __launch_bounds__(256, 2)
gemm_tf32(const float* __restrict__ A, long lda, long strideA,
          const float* __restrict__ B, long ldb, long strideB,
          float* __restrict__ Cm, long ldc, long strideC,
          float alpha,
          const float* __restrict__ bias,
          const float* __restrict__ res) {
    __shared__ __align__(16) float smem[BM * LDA_S + BK * LDB_S]; // 9472 floats
    float* sA = smem;                 // [BM][LDA_S]
    float* sB = smem + BM * LDA_S;    // [BK][LDB_S]
    float* sC = smem;                 // reuse: [64][LDC_S] per wave

    const int bz = blockIdx.z;
    A  += (size_t)bz * strideA;
    B  += (size_t)bz * strideB;
    Cm += (size_t)bz * strideC;
    const float* resb = res ? res + (size_t)bz * strideC : nullptr;

    const int n0 = blockIdx.x * BN;
    const int m0 = blockIdx.y * BM;
    const int tid = threadIdx.x;
    const int wid = tid >> 5;
    const int warp_m = wid & 1;    // 2 warps along M (64 rows each)
    const int warp_n = wid >> 1;   // 4 warps along N (32 cols each)
    const int K = (int)(ACOL ? 0 : 0) + 0; // placeholder (K passed via gridDim trick not used)

    // K is compile-time unknown; pass via constant memory-free approach: derive
    // from launch: we instead pass K through lda? Keep it simple: K in .w of alpha? No.
    // -> We pass K via the unused 'strideA' when batch==1? No. Use a real param:
    // (see wrapper below; K is the 13th parameter)
    // NOTE: this kernel body uses kParam declared below.
    extern __shared__ int _unused[]; (void)_unused;

    // real K comes from gridDim-independent param:
    // (declared after to keep signature; see kParam)
    // -- implemented via additional parameter:
    return; // never used; real kernel below
}

// Real GEMM kernel (explicit K parameter).
template <bool ACOL, bool BCOL>
__global__ void __launch_bounds__(256, 2)
gemm_tf32_k(const float* __restrict__ A, long lda, long strideA,
            const float* __restrict__ B, long ldb, long strideB,
            float* __restrict__ Cm, long ldc, long strideC,
            int K, float alpha,
            const float* __restrict__ bias,
            const float* __restrict__ res) {
    __shared__ __align__(16) float smem[BM * LDA_S + BK * LDB_S];
    float* sA = smem;
    float* sB = smem + BM * LDA_S;
    float* sC = smem;

    const int bz = blockIdx.z;
    A  += (size_t)bz * strideA;
    B  += (size_t)bz * strideB;
    Cm += (size_t)bz * strideC;
    const float* resb = res ? res + (size_t)bz * strideC : nullptr;

    const int n0 = blockIdx.x * BN;
    const int m0 = blockIdx.y * BM;
    const int tid = threadIdx.x;
    const int wid = tid >> 5;
    const int warp_m = wid & 1;
    const int warp_n = wid >> 1;

    wmma::fragment<wmma::accumulator, 16, 16, 8, float> acc[4][2];
    #pragma unroll
    for (int i = 0; i < 4; i++)
        #pragma unroll
        for (int j = 0; j < 2; j++)
            wmma::fill_fragment(acc[i][j], 0.0f);

    for (int k0 = 0; k0 < K; k0 += BK) {
        // ---- load A tile -> sA[m][k]
        if (ACOL) {
            #pragma unroll
            for (int it = 0; it < (BM * BK) / 256; it++) {
                int idx = tid + it * 256;
                int m = idx & (BM - 1);
                int k = idx >> 7;
                sA[m * LDA_S + k] = A[(size_t)(k0 + k) * lda + (m0 + m)];
            }
        } else {
            #pragma unroll
            for (int it = 0; it < (BM * BK) / 256; it++) {
                int idx = tid + it * 256;
                int k = idx & (BK - 1);
                int m = idx >> 5;
                sA[m * LDA_S + k] = A[(size_t)(m0 + m) * lda + (k0 + k)];
            }
        }
        // ---- load B tile -> sB[k][n]
        if (BCOL) {
            #pragma unroll
            for (int it = 0; it < (BK * BN) / 256; it++) {
                int idx = tid + it * 256;
                int k = idx & (BK - 1);
                int n = idx >> 5;
                sB[k * LDB_S + n] = B[(size_t)(n0 + n) * ldb + (k0 + k)];
            }
        } else {
            #pragma unroll
            for (int it = 0; it < (BK * BN) / 256; it++) {
                int idx = tid + it * 256;
                int n = idx & (BN - 1);
                int k = idx >> 7;
                sB[k * LDB_S + n] = B[(size_t)(k0 + k) * ldb + (n0 + n)];
            }
        }
        __syncthreads();
        #pragma unroll
        for (int kk = 0; kk < BK; kk += 8) {
            wmma::fragment<wmma::matrix_a, 16, 16, 8, wmma::precision::tf32, wmma::row_major> af[4];
            wmma::fragment<wmma::matrix_b, 16, 16, 8, wmma::precision::tf32, wmma::row_major> bf[2];
            #pragma unroll
            for (int i = 0; i < 4; i++) {
                wmma::load_matrix_sync(af[i], &sA[(warp_m * 64 + i * 16) * LDA_S + kk], LDA_S);
                #pragma unroll
                for (int e = 0; e < af[i].num_elements; e++)
                    af[i].x[e] = wmma::__float_to_tf32(af[i].x[e]);
            }
            #pragma unroll
            for (int j = 0; j < 2; j++) {
                wmma::load_matrix_sync(bf[j], &sB[kk * LDB_S + warp_n * 32 + j * 16], LDB_S);
                #pragma unroll
                for (int e = 0; e < bf[j].num_elements; e++)
                    bf[j].x[e] = wmma::__float_to_tf32(bf[j].x[e]);
            }
            #pragma unroll
            for (int i = 0; i < 4; i++)
                #pragma unroll
                for (int j = 0; j < 2; j++)
                    wmma::mma_sync(acc[i][j], af[i], bf[j], acc[i][j]);
        }
        __syncthreads();
    }

    // ---- epilogue in two waves (smem reuse, stays under 48KB static)
    #pragma unroll
    for (int wave = 0; wave < 2; wave++) {
        __syncthreads();
        #pragma unroll
        for (int i = 0; i < 2; i++) {
            int ii = wave * 2 + i;
            int r = warp_m * 32 + i * 16;      // local row within the 64-row wave
            #pragma unroll
            for (int j = 0; j < 2; j++)
                wmma::store_matrix_sync(&sC[r * LDC_S + warp_n * 32 + j * 16],
                                        acc[ii][j], LDC_S, wmma::mem_row_major);
        }
        __syncthreads();
        #pragma unroll
        for (int it = 0; it < (64 * BN) / 256; it++) {
            int idx = tid + it * 256;
            int n = idx & (BN - 1);
            int r = idx >> 7;                  // 0..63 local
            // wave0 covers global rows {0..31, 64..95}; wave1 {32..63, 96..127}
            int m = (r < 32 ? r : r + 32) + wave * 32;
            float v = alpha * sC[r * LDC_S + n];
            if (bias) v += bias[m0 + m];
            size_t ci = (size_t)(m0 + m) * ldc + (n0 + n);
            if (resb) v += resb[ci];
            Cm[ci] = v;
        }
    }
}

// ============================ Softmax ============================
// Row-wise softmax over the last dim (1024) of g_P. One warp per row.
__global__ void softmax_kernel(float* __restrict__ P) {
    const int row = blockIdx.x * (blockDim.x >> 5) + (threadIdx.x >> 5);
    const int lane = threadIdx.x & 31;
    if (row >= T * HW) return;
    float4* p4 = (float4*)(P + (size_t)row * HW);

    float4 v[8];
    float m = -1e30f;
    #pragma unroll
    for (int i = 0; i < 8; i++) {
        v[i] = p4[lane + 32 * i];
        m = fmaxf(m, fmaxf(fmaxf(v[i].x, v[i].y), fmaxf(v[i].z, v[i].w)));
    }
    #pragma unroll
    for (int o = 16; o > 0; o >>= 1)
        m = fmaxf(m, __shfl_xor_sync(0xffffffffu, m, o));

    float sum = 0.f;
    #pragma unroll
    for (int i = 0; i < 8; i++) {
        v[i].x = expf(v[i].x - m); v[i].y = expf(v[i].y - m);
        v[i].z = expf(v[i].z - m); v[i].w = expf(v[i].w - m);
        sum += v[i].x + v[i].y + v[i].z + v[i].w;
    }
    #pragma unroll
    for (int o = 16; o > 0; o >>= 1)
        sum += __shfl_xor_sync(0xffffffffu, sum, o);
    const float inv = 1.0f / sum;
    #pragma unroll
    for (int i = 0; i < 8; i++) {
        v[i].x *= inv; v[i].y *= inv; v[i].z *= inv; v[i].w *= inv;
        p4[lane + 32 * i] = v[i];
    }
}

// ============================ launch ============================
extern "C" void kernel_launch(void* const* d_in, const int* in_sizes, int n_in,
                              void* d_out, int out_size) {
    const float* x     = (const float*)d_in[0];
    const float* gamma = (const float*)d_in[1];
    const float* beta  = (const float*)d_in[2];
    const float* wq    = (const float*)d_in[3];
    const float* bq    = (const float*)d_in[4];
    const float* wk    = (const float*)d_in[5];
    const float* bk    = (const float*)d_in[6];
    const float* wv    = (const float*)d_in[7];
    const float* bv    = (const float*)d_in[8];
    const float* wo    = (const float*)d_in[9];
    const float* bo    = (const float*)d_in[10];
    float* out = (float*)d_out;

    float *H, *Q, *Kb, *V, *O, *P;
    cudaGetSymbolAddress((void**)&H,  g_H);
    cudaGetSymbolAddress((void**)&Q,  g_Q);
    cudaGetSymbolAddress((void**)&Kb, g_K);
    cudaGetSymbolAddress((void**)&V,  g_V);
    cudaGetSymbolAddress((void**)&O,  g_O);
    cudaGetSymbolAddress((void**)&P,  g_P);

    // 1) GroupNorm -> H  [c][s]
    gn_kernel<<<NGROUPS, 1024>>>(x, gamma, beta, H);

    // 2) Q/K/V = W @ H + b      (M=512, N=16384, K=512)
    {
        dim3 grid(S_TOT / BN, C / BM, 1);
        gemm_tf32_k<false, false><<<grid, 256>>>(wq, C, 0, H, S_TOT, 0, Q,  S_TOT, 0, C, 1.0f, bq, nullptr);
        gemm_tf32_k<false, false><<<grid, 256>>>(wk, C, 0, H, S_TOT, 0, Kb, S_TOT, 0, C, 1.0f, bk, nullptr);
        gemm_tf32_k<false, false><<<grid, 256>>>(wv, C, 0, H, S_TOT, 0, V,  S_TOT, 0, C, 1.0f, bv, nullptr);
    }

    // 3) S = scale * Qf^T Kf per frame  (M=1024, N=1024, K=512, batch=16)
    {
        const float scale = 0.044194173824159216f; // 512^-0.5
        dim3 grid(HW / BN, HW / BM, T);
        gemm_tf32_k<true, false><<<grid, 256>>>(Q, S_TOT, HW, Kb, S_TOT, HW,
                                                P, HW, (long)HW * HW,
                                                C, scale, nullptr, nullptr);
    }

    // 4) row softmax on P
    softmax_kernel<<<(T * HW) / 8, 256>>>(P);

    // 5) O = Vf @ Pf^T per frame  (M=512, N=1024, K=1024, batch=16)
    {
        dim3 grid(HW / BN, C / BM, T);
        gemm_tf32_k<false, true><<<grid, 256>>>(V, S_TOT, HW, P, HW, (long)HW * HW,
                                                O, S_TOT, HW,
                                                HW, 1.0f, nullptr, nullptr);
    }

    // 6) out = wo @ O + bo + x   (M=512, N=16384, K=512, residual)
    {
        dim3 grid(S_TOT / BN, C / BM, 1);
        gemm_tf32_k<false, false><<<grid, 256>>>(wo, C, 0, O, S_TOT, 0,
                                                 out, S_TOT, 0,
                                                 C, 1.0f, bo, x);
    }
}

// round 3
// speedup vs baseline: 1.2650x; 1.2650x over previous
#include <cuda_runtime.h>
#include <cuda_bf16.h>
#include <mma.h>
#include <math.h>
#include <type_traits>

using namespace nvcuda;

// Problem sizes (fixed by setup_inputs)
#define C        512
#define T        16
#define HW       1024          // 32*32 tokens per frame
#define S_TOT    (T * HW)      // 16384 spatial positions
#define NGROUPS  32
#define CPG      (C / NGROUPS) // 16 channels per group
#define GELEMS   (CPG * S_TOT) // 262144 elements per group
#define EPS      1e-6f

// ---------------- scratch (device globals; allocation-free) ----------------
__device__ __align__(16) float g_Q[(size_t)C * S_TOT];   // q        [c][s]
__device__ __align__(16) float g_K[(size_t)C * S_TOT];   // k        [c][s]
__device__ __align__(16) float g_V[(size_t)C * S_TOT];   // v        [c][s]
__device__ __align__(16) float g_O[(size_t)C * S_TOT];   // attn out [c][s]
__device__ __align__(16) float g_P[(size_t)T * HW * HW]; // probs    [f][i][j]
__device__ __align__(16) float2 g_part[NGROUPS * 16];    // partial (sum, sumsq)
__device__ __align__(16) float  g_ga[C];                 // gamma*rstd per channel
__device__ __align__(16) float  g_be[C];                 // beta - mean*ga per channel

// ============================ GroupNorm phase A: partial sums ============================
__global__ void gn_partial(const float* __restrict__ x, float2* __restrict__ part) {
    const int g  = blockIdx.y;
    const int ch = blockIdx.x;                 // 16 chunks per group
    const int tid = threadIdx.x;               // 256 threads
    const float4* xp = (const float4*)(x + (size_t)g * GELEMS) + (size_t)ch * 4096;

    float s = 0.f, ss = 0.f;
    #pragma unroll 4
    for (int i = tid; i < 4096; i += 256) {
        float4 v = xp[i];
        s  += v.x + v.y + v.z + v.w;
        ss += v.x * v.x + v.y * v.y + v.z * v.z + v.w * v.w;
    }
    __shared__ float sh1[8], sh2[8];
    const int lane = tid & 31, wid = tid >> 5;
    #pragma unroll
    for (int o = 16; o > 0; o >>= 1) {
        s  += __shfl_xor_sync(0xffffffffu, s, o);
        ss += __shfl_xor_sync(0xffffffffu, ss, o);
    }
    if (lane == 0) { sh1[wid] = s; sh2[wid] = ss; }
    __syncthreads();
    if (tid == 0) {
        s = 0.f; ss = 0.f;
        #pragma unroll
        for (int i = 0; i < 8; i++) { s += sh1[i]; ss += sh2[i]; }
        part[g * 16 + ch] = make_float2(s, ss);
    }
}

// ============================ GroupNorm phase B: per-channel affine ============================
__global__ void gn_finalize(const float2* __restrict__ part,
                            const float* __restrict__ gamma,
                            const float* __restrict__ beta,
                            float* __restrict__ ga, float* __restrict__ be) {
    const int c = threadIdx.x;     // 512 threads, one block
    const int g = c >> 4;
    float s = 0.f, ss = 0.f;
    #pragma unroll
    for (int i = 0; i < 16; i++) { float2 p = part[g * 16 + i]; s += p.x; ss += p.y; }
    const float mean = s * (1.0f / GELEMS);
    const float var  = ss * (1.0f / GELEMS) - mean * mean;
    const float rstd = rsqrtf(var + EPS);
    const float gav = gamma[c] * rstd;
    ga[c] = gav;
    be[c] = beta[c] - mean * gav;
}

// ============================ tf32 WMMA GEMM (double-buffered) ============================
// C[m][n] (+batch z) = alpha * sum_k A(m,k) B(k,n) [+ bias[m]] [+ res[m][n]]
// ACOL: A element (m,k) at A + k*lda + m   else A + m*lda + k
// BCOL: B element (k,n) at B + n*ldb + k   else B + k*ldb + n
// If ga != nullptr (requires !BCOL), B is read as x and normalized on the fly:
//   B(k,n) := x[k*ldb+n] * ga[k] + be[k]   (k is the channel index; k0 global)
#define BM 128
#define BN 128
#define BK 16

template <bool ACOL, bool BCOL>
__global__ void __launch_bounds__(256, 2)
gemm_v2(const float* __restrict__ A, long lda, long strideA,
        const float* __restrict__ B, long ldb, long strideB,
        float* __restrict__ Cm, long ldc, long strideC,
        int K, float alpha,
        const float* __restrict__ bias,
        const float* __restrict__ res,
        const float* __restrict__ ga,
        const float* __restrict__ be) {
    constexpr int ASZ = ACOL ? (BK * 132) : (BM * 20);
    constexpr int BSZ = BCOL ? (BN * 20) : (BK * 132);
    constexpr int STAGE = ASZ + BSZ;
    __shared__ __align__(16) float smem[2 * STAGE];

    const int bz = blockIdx.z;
    const float* Ab = A + (size_t)bz * strideA;
    const float* Bb = B + (size_t)bz * strideB;
    float* Cb = Cm + (size_t)bz * strideC;
    const float* resb = res ? res + (size_t)bz * strideC : nullptr;

    const int n0 = blockIdx.x * BN;
    const int m0 = blockIdx.y * BM;
    const int tid = threadIdx.x;
    const int lane = tid & 31;
    const int wid = tid >> 5;
    const int warp_m = wid & 1;    // 2 warps along M (64 rows each)
    const int warp_n = wid >> 1;   // 4 warps along N (32 cols each)

    using AFrag = wmma::fragment<wmma::matrix_a, 16, 16, 8, wmma::precision::tf32,
        typename std::conditional<ACOL, wmma::col_major, wmma::row_major>::type>;
    using BFrag = wmma::fragment<wmma::matrix_b, 16, 16, 8, wmma::precision::tf32,
        typename std::conditional<BCOL, wmma::col_major, wmma::row_major>::type>;

    wmma::fragment<wmma::accumulator, 16, 16, 8, float> acc[4][2];
    #pragma unroll
    for (int i = 0; i < 4; i++)
        #pragma unroll
        for (int j = 0; j < 2; j++)
            wmma::fill_fragment(acc[i][j], 0.0f);

    const int nk = K >> 4;

    // ---- tile load/store helpers (2 float4 per thread per tile) ----
    auto loadA = [&](int k0, float4* ra) {
        #pragma unroll
        for (int it = 0; it < 2; it++) {
            int idx = tid + it * 256;
            if (ACOL) { int k = idx >> 5, mq = idx & 31;
                ra[it] = *(const float4*)&Ab[(size_t)(k0 + k) * lda + m0 + mq * 4];
            } else { int m = idx >> 2, kq = idx & 3;
                ra[it] = *(const float4*)&Ab[(size_t)(m0 + m) * lda + k0 + kq * 4];
            }
        }
    };
    auto loadB = [&](int k0, float4* rb) {
        #pragma unroll
        for (int it = 0; it < 2; it++) {
            int idx = tid + it * 256;
            if (BCOL) { int n = idx >> 2, kq = idx & 3;
                rb[it] = *(const float4*)&Bb[(size_t)(n0 + n) * ldb + k0 + kq * 4];
            } else { int k = idx >> 5, nq = idx & 31;
                rb[it] = *(const float4*)&Bb[(size_t)(k0 + k) * ldb + n0 + nq * 4];
            }
        }
    };
    auto storeA = [&](float4* ra, float* sA) {
        #pragma unroll
        for (int it = 0; it < 2; it++) {
            int idx = tid + it * 256;
            float4 v = ra[it];
            v.x = wmma::__float_to_tf32(v.x); v.y = wmma::__float_to_tf32(v.y);
            v.z = wmma::__float_to_tf32(v.z); v.w = wmma::__float_to_tf32(v.w);
            if (ACOL) { int k = idx >> 5, mq = idx & 31;
                *(float4*)&sA[k * 132 + mq * 4] = v;
            } else { int m = idx >> 2, kq = idx & 3;
                *(float4*)&sA[m * 20 + kq * 4] = v;
            }
        }
    };
    auto storeB = [&](int k0, float4* rb, float* sB) {
        #pragma unroll
        for (int it = 0; it < 2; it++) {
            int idx = tid + it * 256;
            float4 v = rb[it];
            if (!BCOL && ga) {          // fused GroupNorm on x
                int k = idx >> 5;
                const int c = k0 + k;
                const float gav = ga[c], bev = be[c];
                v.x = v.x * gav + bev; v.y = v.y * gav + bev;
                v.z = v.z * gav + bev; v.w = v.w * gav + bev;
            }
            v.x = wmma::__float_to_tf32(v.x); v.y = wmma::__float_to_tf32(v.y);
            v.z = wmma::__float_to_tf32(v.z); v.w = wmma::__float_to_tf32(v.w);
            if (BCOL) { int n = idx >> 2, kq = idx & 3;
                *(float4*)&sB[n * 20 + kq * 4] = v;
            } else { int k = idx >> 5, nq = idx & 31;
                *(float4*)&sB[k * 132 + nq * 4] = v;
            }
        }
    };

    // ---- prologue: tile 0 ----
    {
        float4 ra[2], rb[2];
        loadA(0, ra); loadB(0, rb);
        storeA(ra, smem); storeB(0, rb, smem + ASZ);
    }
    __syncthreads();

    // ---- main loop ----
    for (int kt = 0; kt < nk; kt++) {
        const int cur = kt & 1;
        const int nxt = cur ^ 1;
        float* sA_c = smem + cur * STAGE;
        float* sB_c = smem + cur * STAGE + ASZ;

        float4 ra[2], rb[2];
        const bool more = (kt + 1 < nk);
        const int k0n = (kt + 1) << 4;
        if (more) { loadA(k0n, ra); loadB(k0n, rb); }

        #pragma unroll
        for (int kk = 0; kk < BK; kk += 8) {
            AFrag af[4];
            BFrag bf[2];
            #pragma unroll
            for (int i = 0; i < 4; i++) {
                const int mr = warp_m * 64 + i * 16;
                const float* pa = ACOL ? &sA_c[kk * 132 + mr] : &sA_c[mr * 20 + kk];
                wmma::load_matrix_sync(af[i], pa, ACOL ? 132 : 20);
            }
            #pragma unroll
            for (int j = 0; j < 2; j++) {
                const int nc = warp_n * 32 + j * 16;
                const float* pb = BCOL ? &sB_c[nc * 20 + kk] : &sB_c[kk * 132 + nc];
                wmma::load_matrix_sync(bf[j], pb, BCOL ? 20 : 132);
            }
            #pragma unroll
            for (int i = 0; i < 4; i++)
                #pragma unroll
                for (int j = 0; j < 2; j++)
                    wmma::mma_sync(acc[i][j], af[i], bf[j], acc[i][j]);
        }

        if (more) {
            float* sA_n = smem + nxt * STAGE;
            storeA(ra, sA_n);
            storeB(k0n, rb, sA_n + ASZ);
        }
        __syncthreads();
    }

    // ---- epilogue: per-warp staging through (reused) smem ----
    float* stg = smem + wid * 320;     // 16 x 20 floats per warp
    #pragma unroll
    for (int i = 0; i < 4; i++) {
        #pragma unroll
        for (int j = 0; j < 2; j++) {
            #pragma unroll
            for (int e = 0; e < 8; e++) acc[i][j].x[e] *= alpha;
            wmma::store_matrix_sync(stg, acc[i][j], 20, wmma::mem_row_major);
            __syncwarp();
            const int m_base = m0 + warp_m * 64 + i * 16;
            const int n_base = n0 + warp_n * 32 + j * 16;
            #pragma unroll
            for (int r = 0; r < 8; r++) {
                const int idx = lane + 32 * r;
                const int rr = idx >> 4, cc = idx & 15;
                float v = stg[rr * 20 + cc];
                const int m = m_base + rr, n = n_base + cc;
                if (bias) v += bias[m];
                const size_t ci = (size_t)m * ldc + n;
                if (resb) v += resb[ci];
                Cb[ci] = v;
            }
            __syncwarp();
        }
    }
}

// ============================ Softmax ============================
__global__ void softmax_kernel(float* __restrict__ P) {
    const int row = blockIdx.x * (blockDim.x >> 5) + (threadIdx.x >> 5);
    const int lane = threadIdx.x & 31;
    if (row >= T * HW) return;
    float4* p4 = (float4*)(P + (size_t)row * HW);

    float4 v[8];
    float m = -1e30f;
    #pragma unroll
    for (int i = 0; i < 8; i++) {
        v[i] = p4[lane + 32 * i];
        m = fmaxf(m, fmaxf(fmaxf(v[i].x, v[i].y), fmaxf(v[i].z, v[i].w)));
    }
    #pragma unroll
    for (int o = 16; o > 0; o >>= 1)
        m = fmaxf(m, __shfl_xor_sync(0xffffffffu, m, o));

    float sum = 0.f;
    #pragma unroll
    for (int i = 0; i < 8; i++) {
        v[i].x = __expf(v[i].x - m); v[i].y = __expf(v[i].y - m);
        v[i].z = __expf(v[i].z - m); v[i].w = __expf(v[i].w - m);
        sum += v[i].x + v[i].y + v[i].z + v[i].w;
    }
    #pragma unroll
    for (int o = 16; o > 0; o >>= 1)
        sum += __shfl_xor_sync(0xffffffffu, sum, o);
    const float inv = 1.0f / sum;
    #pragma unroll
    for (int i = 0; i < 8; i++) {
        v[i].x *= inv; v[i].y *= inv; v[i].z *= inv; v[i].w *= inv;
        p4[lane + 32 * i] = v[i];
    }
}

// ============================ launch ============================
extern "C" void kernel_launch(void* const* d_in, const int* in_sizes, int n_in,
                              void* d_out, int out_size) {
    const float* x     = (const float*)d_in[0];
    const float* gamma = (const float*)d_in[1];
    const float* beta  = (const float*)d_in[2];
    const float* wq    = (const float*)d_in[3];
    const float* bq    = (const float*)d_in[4];
    const float* wk    = (const float*)d_in[5];
    const float* bk    = (const float*)d_in[6];
    const float* wv    = (const float*)d_in[7];
    const float* bv    = (const float*)d_in[8];
    const float* wo    = (const float*)d_in[9];
    const float* bo    = (const float*)d_in[10];
    float* out = (float*)d_out;

    float *Q, *Kb, *V, *O, *P, *ga, *be;
    float2* part;
    cudaGetSymbolAddress((void**)&Q,    g_Q);
    cudaGetSymbolAddress((void**)&Kb,   g_K);
    cudaGetSymbolAddress((void**)&V,    g_V);
    cudaGetSymbolAddress((void**)&O,    g_O);
    cudaGetSymbolAddress((void**)&P,    g_P);
    cudaGetSymbolAddress((void**)&part, g_part);
    cudaGetSymbolAddress((void**)&ga,   g_ga);
    cudaGetSymbolAddress((void**)&be,   g_be);

    // 1) GroupNorm stats (deterministic two-phase)
    gn_partial<<<dim3(16, NGROUPS), 256>>>(x, part);
    gn_finalize<<<1, C>>>(part, gamma, beta, ga, be);

    // 2) Q/K/V = W @ GN(x) + b   (M=512, N=16384, K=512; GN fused into B load)
    {
        dim3 grid(S_TOT / BN, C / BM, 1);
        gemm_v2<false, false><<<grid, 256>>>(wq, C, 0, x, S_TOT, 0, Q,  S_TOT, 0,
                                             C, 1.0f, bq, nullptr, ga, be);
        gemm_v2<false, false><<<grid, 256>>>(wk, C, 0, x, S_TOT, 0, Kb, S_TOT, 0,
                                             C, 1.0f, bk, nullptr, ga, be);
        gemm_v2<false, false><<<grid, 256>>>(wv, C, 0, x, S_TOT, 0, V,  S_TOT, 0,
                                             C, 1.0f, bv, nullptr, ga, be);
    }

    // 3) S = scale * Qf^T Kf per frame  (M=1024, N=1024, K=512, batch=16)
    {
        const float scale = 0.044194173824159216f; // 512^-0.5
        dim3 grid(HW / BN, HW / BM, T);
        gemm_v2<true, false><<<grid, 256>>>(Q, S_TOT, HW, Kb, S_TOT, HW,
                                            P, HW, (long)HW * HW,
                                            C, scale, nullptr, nullptr, nullptr, nullptr);
    }

    // 4) row softmax on P
    softmax_kernel<<<(T * HW) / 8, 256>>>(P);

    // 5) O = Vf @ Pf^T per frame  (M=512, N=1024, K=1024, batch=16)
    {
        dim3 grid(HW / BN, C / BM, T);
        gemm_v2<false, true><<<grid, 256>>>(V, S_TOT, HW, P, HW, (long)HW * HW,
                                            O, S_TOT, HW,
                                            HW, 1.0f, nullptr, nullptr, nullptr, nullptr);
    }

    // 6) out = wo @ O + bo + x   (M=512, N=16384, K=512, residual)
    {
        dim3 grid(S_TOT / BN, C / BM, 1);
        gemm_v2<false, false><<<grid, 256>>>(wo, C, 0, O, S_TOT, 0,
                                             out, S_TOT, 0,
                                             C, 1.0f, bo, x, nullptr, nullptr);
    }
}